// round 3
// baseline (speedup 1.0000x reference)
#include <cuda_runtime.h>
#include <math.h>

#define B_ 128
#define T_ 512
#define D_ 128
#define H_ 512
#define G_ 2048          // 4*H
#define EPS_ 1e-3f
#define NBLK_ 128        // persistent scan grid (<= 148 SMs -> fully resident)

// ---------------- scratch (static device allocations; no cudaMalloc) --------
__device__ __align__(16) float g_xz[(size_t)B_ * T_ * G_];    // xz per layer; reused as attention 'e'
__device__ __align__(16) float g_seqA[(size_t)B_ * T_ * H_];
__device__ __align__(16) float g_seqB[(size_t)B_ * T_ * H_];
__device__ __align__(16) float g_h[B_ * H_];
__device__ __align__(16) float g_c[B_ * H_];
__device__ __align__(16) float g_part[4 * B_ * G_];           // split-K partials (deterministic)
__device__ __align__(16) float g_s[B_ * T_];
__device__ __align__(16) float g_pool[B_ * H_];

// ---------------- software grid barrier (sense-reversing, fully-resident grid)
__device__ volatile int g_bar_count;
__device__ volatile int g_bar_sense;

__device__ __forceinline__ void grid_bar(int& ls) {
  __syncthreads();
  if (threadIdx.x == 0) {
    __threadfence();
    const int s = ls ^ 1;
    ls = s;
    if (atomicAdd((int*)&g_bar_count, 1) == NBLK_ - 1) {
      g_bar_count = 0;
      __threadfence();
      g_bar_sense = s;
    } else {
      while (g_bar_sense != s) { }
    }
    __threadfence();
  }
  __syncthreads();
}

// ---------------- generic fp32 GEMM: C = A[M,K] @ W[K,N] + bias, optional tanh
// BM=128, BN=128, BK=8, 256 threads, 8x8 per thread.
template <bool TANH>
__global__ __launch_bounds__(256) void gemm_bias(
    const float* __restrict__ A, const float* __restrict__ W,
    const float* __restrict__ bias, float* __restrict__ C,
    int K, int N) {
  __shared__ float As[8][128];
  __shared__ float Bs[8][128];
  const int tid = threadIdx.x;
  const int tx = tid & 15, ty = tid >> 4;
  const int row0 = blockIdx.y * 128;
  const int col0 = blockIdx.x * 128;
  const int ar = tid >> 1, ak = (tid & 1) * 4;
  const int wk = tid >> 5, wn = (tid & 31) * 4;
  const float* Ap = A + (size_t)(row0 + ar) * K + ak;
  const float* Wp = W + (size_t)wk * N + col0 + wn;

  float acc[8][8];
#pragma unroll
  for (int i = 0; i < 8; i++)
#pragma unroll
    for (int j = 0; j < 8; j++) acc[i][j] = 0.f;

  const int nk = K >> 3;
  float4 pa = *(const float4*)Ap;
  float4 pb = *(const float4*)Wp;
  for (int kt = 0; kt < nk; kt++) {
    __syncthreads();
    As[ak + 0][ar] = pa.x; As[ak + 1][ar] = pa.y;
    As[ak + 2][ar] = pa.z; As[ak + 3][ar] = pa.w;
    *(float4*)&Bs[wk][wn] = pb;
    __syncthreads();
    if (kt + 1 < nk) {
      pa = *(const float4*)(Ap + (kt + 1) * 8);
      pb = *(const float4*)(Wp + (size_t)(kt + 1) * 8 * N);
    }
#pragma unroll
    for (int k = 0; k < 8; k++) {
      float a[8], b[8];
      *(float4*)&a[0] = *(const float4*)&As[k][ty * 4];
      *(float4*)&a[4] = *(const float4*)&As[k][64 + ty * 4];
      *(float4*)&b[0] = *(const float4*)&Bs[k][tx * 4];
      *(float4*)&b[4] = *(const float4*)&Bs[k][64 + tx * 4];
#pragma unroll
      for (int i = 0; i < 8; i++)
#pragma unroll
        for (int j = 0; j < 8; j++) acc[i][j] += a[i] * b[j];
    }
  }
#pragma unroll
  for (int ig = 0; ig < 2; ig++) {
#pragma unroll
    for (int i = 0; i < 4; i++) {
      const int r = row0 + ig * 64 + ty * 4 + i;
#pragma unroll
      for (int jg = 0; jg < 2; jg++) {
        float4 v;
        float* vp = &v.x;
#pragma unroll
        for (int j = 0; j < 4; j++) {
          const int cc = col0 + jg * 64 + tx * 4 + j;
          float t = acc[ig * 4 + i][jg * 4 + j] + bias[cc];
          vp[j] = TANH ? tanhf(t) : t;
        }
        *(float4*)&C[(size_t)r * N + col0 + jg * 64 + tx * 4] = v;
      }
    }
  }
}

// ---------------- persistent LSTM layer: whole T=512 scan in ONE kernel -----
// 128 blocks x 256 threads. Block (kc = bid>>5, colblk = bid&31):
//   GEMM phase: part[kc][0:128][col0:col0+64] = h[:, kc*128:+128] @ U-chunk
//     (U-chunk cached in smem ONCE for the whole layer)
//   barrier -> gate phase (block b=bid handles batch b, 512 gates) -> barrier
__global__ __launch_bounds__(256) void lstm_layer_persist(
    const float* __restrict__ xz, const float* __restrict__ U,
    float* __restrict__ seq, float* __restrict__ h, float* __restrict__ c,
    float* __restrict__ part,
    const float* __restrict__ bng, const float* __restrict__ bnb,
    const float* __restrict__ bnm, const float* __restrict__ bnv,
    int apply_bn) {
  __shared__ float Bs[128][64];  // U tile: K-chunk 128 x 64 cols (32 KB)
  __shared__ float As[8][128];   // h staging tile

  const int bid = blockIdx.x, tid = threadIdx.x;
  const int colblk = bid & 31, kc = bid >> 5;
  const int col0 = colblk * 64, k0 = kc * 128;
  const int tx = tid & 15, ty = tid >> 4;
  const int ar = tid >> 1, ak = (tid & 1) * 4;

  // load U tile once per layer
  for (int i = tid; i < 128 * 16; i += 256) {
    const int k = i >> 4, j4 = (i & 15) * 4;
    *(float4*)&Bs[k][j4] = *(const float4*)&U[(size_t)(k0 + k) * G_ + col0 + j4];
  }

  int ls = 0;
  if (tid == 0) ls = g_bar_sense;  // entry sense (read before first arrival)

  // zero this block's h/c slice (batch row b = bid)
  for (int i = tid; i < H_; i += 256) {
    h[bid * H_ + i] = 0.f;
    c[bid * H_ + i] = 0.f;
  }
  grid_bar(ls);

  float* pp = part + (size_t)kc * B_ * G_;

  for (int t = 0; t < T_; t++) {
    // ---- GEMM phase: partial = h[:, k0:k0+128] @ Bs ----
    float acc[8][4];
#pragma unroll
    for (int i = 0; i < 8; i++)
#pragma unroll
      for (int j = 0; j < 4; j++) acc[i][j] = 0.f;

    float4 pa = *(const float4*)&h[(size_t)ar * H_ + k0 + ak];
#pragma unroll 1
    for (int kt = 0; kt < 16; kt++) {
      __syncthreads();
      As[ak + 0][ar] = pa.x; As[ak + 1][ar] = pa.y;
      As[ak + 2][ar] = pa.z; As[ak + 3][ar] = pa.w;
      __syncthreads();
      if (kt + 1 < 16)
        pa = *(const float4*)&h[(size_t)ar * H_ + k0 + (kt + 1) * 8 + ak];
#pragma unroll
      for (int k = 0; k < 8; k++) {
        float a[8], b[4];
        *(float4*)&a[0] = *(const float4*)&As[k][ty * 4];
        *(float4*)&a[4] = *(const float4*)&As[k][64 + ty * 4];
        *(float4*)&b[0] = *(const float4*)&Bs[kt * 8 + k][tx * 4];
#pragma unroll
        for (int i = 0; i < 8; i++)
#pragma unroll
          for (int j = 0; j < 4; j++) acc[i][j] += a[i] * b[j];
      }
    }
#pragma unroll
    for (int ig = 0; ig < 2; ig++) {
#pragma unroll
      for (int i = 0; i < 4; i++) {
        const int r = ig * 64 + ty * 4 + i;
        *(float4*)&pp[(size_t)r * G_ + col0 + tx * 4] =
            *(float4*)&acc[ig * 4 + i][0];
      }
    }
    grid_bar(ls);  // partials visible

    // ---- gate phase: batch b = bid, gates j = tid, tid+256 ----
    {
      const int b = bid;
      const float* xzp = xz + ((size_t)b * T_ + t) * G_;
#pragma unroll
      for (int half = 0; half < 2; half++) {
        const int j = tid + half * 256;
        float zi = xzp[j], zf = xzp[j + 512], zg = xzp[j + 1024],
              zo = xzp[j + 1536];
#pragma unroll
        for (int s = 0; s < 4; s++) {
          const float* ps = part + ((size_t)s * B_ + b) * G_;
          zi += ps[j]; zf += ps[j + 512]; zg += ps[j + 1024]; zo += ps[j + 1536];
        }
        const float ig = 1.f / (1.f + expf(-zi));
        const float fg = 1.f / (1.f + expf(-zf));
        const float gg = tanhf(zg);
        const float og = 1.f / (1.f + expf(-zo));
        const float cn = fg * c[b * H_ + j] + ig * gg;
        const float hn = og * tanhf(cn);
        c[b * H_ + j] = cn;
        h[b * H_ + j] = hn;
        float outv = hn;
        if (apply_bn)
          outv = (hn - bnm[j]) * rsqrtf(bnv[j] + EPS_) * bng[j] + bnb[j];
        seq[((size_t)b * T_ + t) * H_ + j] = outv;
      }
    }
    grid_bar(ls);  // h(t+1) visible before next GEMM phase
  }
}

// ---------------- attention tail ------------------------------------------
__global__ __launch_bounds__(256) void rowsum_kernel(const float* __restrict__ e,
                                                     float* __restrict__ s) {
  const int row = blockIdx.x * 8 + (threadIdx.x >> 5);
  const int lane = threadIdx.x & 31;
  const float* p = e + (size_t)row * H_;
  float acc = 0.f;
  for (int j = lane; j < H_; j += 32) acc += p[j];
#pragma unroll
  for (int o = 16; o; o >>= 1) acc += __shfl_xor_sync(0xFFFFFFFFu, acc, o);
  if (lane == 0) s[row] = acc;
}

__global__ __launch_bounds__(512) void softmax_kernel(float* __restrict__ s) {
  __shared__ float red[T_];
  const int b = blockIdx.x, t = threadIdx.x;
  const float v = s[b * T_ + t];
  red[t] = v;
  __syncthreads();
  for (int o = 256; o; o >>= 1) {
    if (t < o) red[t] = fmaxf(red[t], red[t + o]);
    __syncthreads();
  }
  const float m = red[0];
  __syncthreads();
  const float ev = expf(v - m);
  red[t] = ev;
  __syncthreads();
  for (int o = 256; o; o >>= 1) {
    if (t < o) red[t] += red[t + o];
    __syncthreads();
  }
  s[b * T_ + t] = ev / red[0];
}

__global__ __launch_bounds__(512) void pool_kernel(const float* __restrict__ seq,
                                                   const float* __restrict__ a,
                                                   float* __restrict__ pool) {
  const int b = blockIdx.x, d = threadIdx.x;
  const float* p = seq + (size_t)b * T_ * H_ + d;
  const float* ap = a + b * T_;
  float acc = 0.f;
  for (int t = 0; t < T_; t++) acc += ap[t] * p[(size_t)t * H_];
  pool[b * H_ + d] = acc * (1.0f / T_);
}

// ---------------- dense head ----------------------------------------------
__global__ __launch_bounds__(128) void head_kernel(
    const float* __restrict__ pool,
    const float* __restrict__ Wd1, const float* __restrict__ bd1,
    const float* __restrict__ bng, const float* __restrict__ bnb,
    const float* __restrict__ bnm, const float* __restrict__ bnv,
    const float* __restrict__ Wd2, const float* __restrict__ bd2,
    const float* __restrict__ Wd3, const float* __restrict__ bd3,
    float* __restrict__ out) {
  __shared__ float sp[H_];
  __shared__ float d1[128];
  __shared__ float d2[64];
  const int b = blockIdx.x, t = threadIdx.x;
  for (int i = t; i < H_; i += 128) sp[i] = pool[b * H_ + i];
  __syncthreads();
  {
    float acc = bd1[t];
    for (int k = 0; k < H_; k++) acc += sp[k] * Wd1[k * 128 + t];
    acc = fmaxf(acc, 0.f);
    acc = (acc - bnm[t]) * rsqrtf(bnv[t] + EPS_) * bng[t] + bnb[t];
    d1[t] = acc;
  }
  __syncthreads();
  if (t < 64) {
    float acc = bd2[t];
    for (int k = 0; k < 128; k++) acc += d1[k] * Wd2[k * 64 + t];
    d2[t] = fmaxf(acc, 0.f);
  }
  __syncthreads();
  if (t < 5) {
    float acc = bd3[t];
    for (int k = 0; k < 64; k++) acc += d2[k] * Wd3[k * 5 + t];
    out[b * 5 + t] = acc;
  }
}

// ---------------- launch ----------------------------------------------------
extern "C" void kernel_launch(void* const* d_in, const int* in_sizes, int n_in,
                              void* d_out, int out_size) {
  (void)out_size;
  // setup_inputs dict order vs reference-signature order autodetect.
  static const int sig_map[30] = {0, 1, 2, 3, 8, 9, 10, 15, 16, 17,
                                  4, 5, 6, 7, 11, 12, 13, 14, 22, 23,
                                  24, 25, 18, 19, 20, 21, 26, 27, 28, 29};
  const int setup_order = (n_in >= 5 && in_sizes[4] == 1048576) ? 1 : 0;
  const float* in[30];
  for (int i = 0; i < 30; i++)
    in[i] = (const float*)d_in[setup_order ? i : sig_map[i]];

  const float* x = in[0];
  const float* Wl[3] = {in[1], in[4], in[7]};
  const float* Ul[3] = {in[2], in[5], in[8]};
  const float* bl[3] = {in[3], in[6], in[9]};
  const float* bng[3] = {in[10], in[14], in[18]};
  const float* bnb[3] = {in[11], in[15], in[19]};
  const float* bnm[3] = {in[12], in[16], in[20]};
  const float* bnv[3] = {in[13], in[17], in[21]};
  const float* Wa = in[22];  const float* ba = in[23];
  const float* Wd1 = in[24]; const float* bd1 = in[25];
  const float* Wd2 = in[26]; const float* bd2 = in[27];
  const float* Wd3 = in[28]; const float* bd3 = in[29];

  float *xz, *seqA, *seqB, *h, *c, *part, *s, *pool;
  cudaGetSymbolAddress((void**)&xz, g_xz);
  cudaGetSymbolAddress((void**)&seqA, g_seqA);
  cudaGetSymbolAddress((void**)&seqB, g_seqB);
  cudaGetSymbolAddress((void**)&h, g_h);
  cudaGetSymbolAddress((void**)&c, g_c);
  cudaGetSymbolAddress((void**)&part, g_part);
  cudaGetSymbolAddress((void**)&s, g_s);
  cudaGetSymbolAddress((void**)&pool, g_pool);

  const int MROWS = B_ * T_;  // 65536
  float* seq_out[3] = {seqA, seqB, seqA};
  const float* seq_in[3] = {x, seqA, seqB};
  const int Kin[3] = {D_, H_, H_};

  for (int L = 0; L < 3; L++) {
    gemm_bias<false><<<dim3(G_ / 128, MROWS / 128), 256>>>(
        seq_in[L], Wl[L], bl[L], xz, Kin[L], G_);
    const int apply_bn = (L < 2) ? 1 : 0;
    lstm_layer_persist<<<NBLK_, 256>>>(xz, Ul[L], seq_out[L], h, c, part,
                                       bng[L], bnb[L], bnm[L], bnv[L],
                                       apply_bn);
  }

  gemm_bias<true><<<dim3(H_ / 128, MROWS / 128), 256>>>(seqA, Wa, ba, xz, H_, H_);
  rowsum_kernel<<<MROWS / 8, 256>>>(xz, s);
  softmax_kernel<<<B_, T_>>>(s);
  pool_kernel<<<B_, H_>>>(seqA, s, pool);
  head_kernel<<<B_, 128>>>(pool, Wd1, bd1, bng[2], bnb[2], bnm[2], bnv[2],
                           Wd2, bd2, Wd3, bd3, (float*)d_out);
}

// round 5
// speedup vs baseline: 1.8480x; 1.8480x over previous
#include <cuda_runtime.h>
#include <math.h>
#include <stdint.h>

#define B_ 128
#define T_ 512
#define D_ 128
#define H_ 512
#define G_ 2048          // 4*H
#define EPS_ 1e-3f
#define NBLK_ 128        // persistent scan grid (<= 148 SMs -> fully resident)

// ---------------- scratch (static device allocations; no cudaMalloc) --------
__device__ __align__(16) float g_xz[(size_t)B_ * T_ * G_];
__device__ __align__(16) float g_seqA[(size_t)B_ * T_ * H_];
__device__ __align__(16) float g_seqB[(size_t)B_ * T_ * H_];
__device__ __align__(16) float g_h[B_ * H_];
__device__ __align__(16) float g_c[B_ * H_];
__device__ __align__(16) float g_part[4 * B_ * G_];
__device__ __align__(16) float g_s[B_ * T_];
__device__ __align__(16) float g_pool[B_ * H_];
// barrier state
__device__ volatile int g_bar_count;
__device__ volatile int g_bar_sense;
__device__ int g_flags[NBLK_ * 32];  // padded: one 128B line per block

// ---------------- tf32 helpers ---------------------------------------------
__device__ __forceinline__ uint32_t f2tf32(float x) {
  uint32_t u;
  asm("cvt.rna.tf32.f32 %0, %1;" : "=r"(u) : "f"(x));
  return u;
}
__device__ __forceinline__ void mma_tf32(float* d, const uint32_t* a,
                                         const uint32_t* b) {
  asm("mma.sync.aligned.m16n8k8.row.col.f32.tf32.tf32.f32 "
      "{%0,%1,%2,%3}, {%4,%5,%6,%7}, {%8,%9}, {%0,%1,%2,%3};"
      : "+f"(d[0]), "+f"(d[1]), "+f"(d[2]), "+f"(d[3])
      : "r"(a[0]), "r"(a[1]), "r"(a[2]), "r"(a[3]), "r"(b[0]), "r"(b[1]));
}

// ---------------- barriers ---------------------------------------------------
__device__ __forceinline__ void grid_bar_atomic(int& ls) {
  __syncthreads();
  if (threadIdx.x == 0) {
    __threadfence();
    const int s = ls ^ 1;
    ls = s;
    if (atomicAdd((int*)&g_bar_count, 1) == NBLK_ - 1) {
      g_bar_count = 0;
      __threadfence();
      g_bar_sense = s;
    } else {
      while (g_bar_sense != s) { }
    }
    __threadfence();
  }
  __syncthreads();
}

// flag-array barrier: phases strictly increasing within one layer launch.
// Poll uses '<' (monotone) so a fast block writing phase+1 can't strand a
// slow poller (the '!=' version deadlocks).
__device__ __forceinline__ void fast_bar(int phase) {
  __threadfence();   // release: my stores visible before flag store
  __syncthreads();
  if (threadIdx.x == 0)
    *((volatile int*)&g_flags[blockIdx.x * 32]) = phase;
  if (threadIdx.x < NBLK_) {
    while (*((volatile int*)&g_flags[threadIdx.x * 32]) < phase) { }
  }
  __syncthreads();
  if (threadIdx.x == 0) __threadfence();  // acquire
  __syncthreads();
}

// ---------------- tf32 tensor-core GEMM: C = A[M,K]@W[K,N] + bias (opt tanh)
// BM=128, BN=128, BK=32, 256 thr (8 warps, 4x2), warp tile 32x64.
template <bool TANH>
__global__ __launch_bounds__(256) void gemm_tf32(
    const float* __restrict__ A, const float* __restrict__ W,
    const float* __restrict__ bias, float* __restrict__ C, int K, int N) {
  __shared__ uint32_t As[128][36];   // [m][k] (pad 36)
  __shared__ uint32_t Bs[32][136];   // [k][n] (pad 136)
  const int tid = threadIdx.x;
  const int warp = tid >> 5, lane = tid & 31;
  const int wm = warp >> 1, wn = warp & 1;
  const int m0 = wm * 32, n0 = wn * 64;
  const int r = lane >> 2, c4 = lane & 3;
  const int row0 = blockIdx.y * 128, col0 = blockIdx.x * 128;

  float acc[2][8][4];
#pragma unroll
  for (int i = 0; i < 2; i++)
#pragma unroll
    for (int j = 0; j < 8; j++)
#pragma unroll
      for (int k = 0; k < 4; k++) acc[i][j][k] = 0.f;

  const int fA = tid;
  float4 va[4], vb[4];
#pragma unroll
  for (int i = 0; i < 4; i++) {
    const int f = fA + i * 256;
    va[i] = *(const float4*)&A[(size_t)(row0 + (f >> 3)) * K + ((f & 7) << 2)];
    vb[i] = *(const float4*)&W[(size_t)(f >> 5) * N + col0 + ((f & 31) << 2)];
  }

  for (int kt = 0; kt < K; kt += 32) {
    __syncthreads();
#pragma unroll
    for (int i = 0; i < 4; i++) {
      const int f = fA + i * 256;
      const int rA = f >> 3, kq = (f & 7) << 2;
      As[rA][kq + 0] = f2tf32(va[i].x);
      As[rA][kq + 1] = f2tf32(va[i].y);
      As[rA][kq + 2] = f2tf32(va[i].z);
      As[rA][kq + 3] = f2tf32(va[i].w);
      const int kB = f >> 5, nq = (f & 31) << 2;
      Bs[kB][nq + 0] = f2tf32(vb[i].x);
      Bs[kB][nq + 1] = f2tf32(vb[i].y);
      Bs[kB][nq + 2] = f2tf32(vb[i].z);
      Bs[kB][nq + 3] = f2tf32(vb[i].w);
    }
    __syncthreads();
    if (kt + 32 < K) {
#pragma unroll
      for (int i = 0; i < 4; i++) {
        const int f = fA + i * 256;
        va[i] = *(const float4*)&A[(size_t)(row0 + (f >> 3)) * K + kt + 32 +
                                   ((f & 7) << 2)];
        vb[i] = *(const float4*)&W[(size_t)(kt + 32 + (f >> 5)) * N + col0 +
                                   ((f & 31) << 2)];
      }
    }
#pragma unroll
    for (int k8 = 0; k8 < 32; k8 += 8) {
      uint32_t af[2][4], bf[8][2];
#pragma unroll
      for (int mf = 0; mf < 2; mf++) {
        const int ar = m0 + mf * 16 + r;
        af[mf][0] = As[ar][k8 + c4];
        af[mf][1] = As[ar + 8][k8 + c4];
        af[mf][2] = As[ar][k8 + c4 + 4];
        af[mf][3] = As[ar + 8][k8 + c4 + 4];
      }
#pragma unroll
      for (int nf = 0; nf < 8; nf++) {
        bf[nf][0] = Bs[k8 + c4][n0 + nf * 8 + r];
        bf[nf][1] = Bs[k8 + c4 + 4][n0 + nf * 8 + r];
      }
#pragma unroll
      for (int mf = 0; mf < 2; mf++)
#pragma unroll
        for (int nf = 0; nf < 8; nf++) mma_tf32(acc[mf][nf], af[mf], bf[nf]);
    }
  }
#pragma unroll
  for (int mf = 0; mf < 2; mf++) {
#pragma unroll
    for (int nf = 0; nf < 8; nf++) {
      const int cc = col0 + n0 + nf * 8 + c4 * 2;
      const float b0 = bias[cc], b1 = bias[cc + 1];
      const int rr = row0 + m0 + mf * 16 + r;
      float2 v0, v1;
      v0.x = acc[mf][nf][0] + b0; v0.y = acc[mf][nf][1] + b1;
      v1.x = acc[mf][nf][2] + b0; v1.y = acc[mf][nf][3] + b1;
      if (TANH) {
        v0.x = tanhf(v0.x); v0.y = tanhf(v0.y);
        v1.x = tanhf(v1.x); v1.y = tanhf(v1.y);
      }
      *(float2*)&C[(size_t)rr * N + cc] = v0;
      *(float2*)&C[(size_t)(rr + 8) * N + cc] = v1;
    }
  }
}

// ---------------- persistent LSTM layer (tf32 mma GEMM phase) ---------------
#define AS2_STRIDE 132
#define US_STRIDE 72
#define SMEM_SCAN ((128 * AS2_STRIDE + 128 * US_STRIDE) * 4)

__global__ __launch_bounds__(256) void lstm_layer_persist(
    const float* __restrict__ xz, const float* __restrict__ U,
    float* __restrict__ seq, float* __restrict__ h, float* __restrict__ c,
    float* __restrict__ part,
    const float* __restrict__ bng, const float* __restrict__ bnb,
    const float* __restrict__ bnm, const float* __restrict__ bnv,
    int apply_bn) {
  extern __shared__ uint32_t smem[];
  uint32_t (*As2)[AS2_STRIDE] = (uint32_t(*)[AS2_STRIDE])smem;
  uint32_t (*Us)[US_STRIDE] = (uint32_t(*)[US_STRIDE])(smem + 128 * AS2_STRIDE);

  const int bid = blockIdx.x, tid = threadIdx.x;
  const int colblk = bid & 31, kc = bid >> 5;
  const int col0 = colblk * 64, k0 = kc * 128;
  const int warp = tid >> 5, lane = tid & 31;
  const int wm = warp >> 1, wn = warp & 1;
  const int m0 = wm * 32, n0 = wn * 32;
  const int r = lane >> 2, c4 = lane & 3;

  // stage U chunk [k0:+128][col0:+64] once, as tf32
#pragma unroll
  for (int i = 0; i < 8; i++) {
    const int f = tid + i * 256;          // 2048 float4
    const int rU = f >> 4, nq = (f & 15) << 2;
    float4 v = *(const float4*)&U[(size_t)(k0 + rU) * G_ + col0 + nq];
    Us[rU][nq + 0] = f2tf32(v.x);
    Us[rU][nq + 1] = f2tf32(v.y);
    Us[rU][nq + 2] = f2tf32(v.z);
    Us[rU][nq + 3] = f2tf32(v.w);
  }

  int ls = 0;
  if (tid == 0) {
    ls = g_bar_sense;
    g_flags[bid * 32] = 0;   // per-layer reset, published by grid_bar_atomic
  }
  for (int i = tid; i < H_; i += 256) {
    h[bid * H_ + i] = 0.f;
    c[bid * H_ + i] = 0.f;
  }
  grid_bar_atomic(ls);  // flags reset + h/c zero + U staged, all visible

  float* pp = part + (size_t)kc * B_ * G_;

  for (int t = 0; t < T_; t++) {
    // ---- stage h slice [128 b][k0:+128] -> As2 (tf32) ----
#pragma unroll
    for (int i = 0; i < 16; i++) {
      const int f = tid + i * 256;        // 4096 float4
      const int rH = f >> 5, kq = (f & 31) << 2;
      float4 v = *(const float4*)&h[(size_t)rH * H_ + k0 + kq];
      As2[rH][kq + 0] = f2tf32(v.x);
      As2[rH][kq + 1] = f2tf32(v.y);
      As2[rH][kq + 2] = f2tf32(v.z);
      As2[rH][kq + 3] = f2tf32(v.w);
    }
    __syncthreads();

    // ---- mma: [128 x 64] over K=128 ----
    float acc[2][4][4];
#pragma unroll
    for (int i = 0; i < 2; i++)
#pragma unroll
      for (int j = 0; j < 4; j++)
#pragma unroll
        for (int k = 0; k < 4; k++) acc[i][j][k] = 0.f;

#pragma unroll
    for (int k8 = 0; k8 < 128; k8 += 8) {
      uint32_t af[2][4], bf[4][2];
#pragma unroll
      for (int mf = 0; mf < 2; mf++) {
        const int ar = m0 + mf * 16 + r;
        af[mf][0] = As2[ar][k8 + c4];
        af[mf][1] = As2[ar + 8][k8 + c4];
        af[mf][2] = As2[ar][k8 + c4 + 4];
        af[mf][3] = As2[ar + 8][k8 + c4 + 4];
      }
#pragma unroll
      for (int nf = 0; nf < 4; nf++) {
        bf[nf][0] = Us[k8 + c4][n0 + nf * 8 + r];
        bf[nf][1] = Us[k8 + c4 + 4][n0 + nf * 8 + r];
      }
#pragma unroll
      for (int mf = 0; mf < 2; mf++)
#pragma unroll
        for (int nf = 0; nf < 4; nf++) mma_tf32(acc[mf][nf], af[mf], bf[nf]);
    }
#pragma unroll
    for (int mf = 0; mf < 2; mf++) {
#pragma unroll
      for (int nf = 0; nf < 4; nf++) {
        const int cc = col0 + n0 + nf * 8 + c4 * 2;
        const int b0r = m0 + mf * 16 + r;
        *(float2*)&pp[(size_t)b0r * G_ + cc] =
            make_float2(acc[mf][nf][0], acc[mf][nf][1]);
        *(float2*)&pp[(size_t)(b0r + 8) * G_ + cc] =
            make_float2(acc[mf][nf][2], acc[mf][nf][3]);
      }
    }
    __syncthreads();
    fast_bar(2 * t + 1);

    // ---- gate phase: batch b = bid, cols 2*tid, 2*tid+1 ----
    {
      const int b = bid;
      const float2* xz2 = (const float2*)(xz + ((size_t)b * T_ + t) * G_);
      float2 zi = xz2[tid], zf = xz2[256 + tid], zg = xz2[512 + tid],
             zo = xz2[768 + tid];
#pragma unroll
      for (int s = 0; s < 4; s++) {
        const float2* p2 = (const float2*)(part + ((size_t)s * B_ + b) * G_);
        float2 a = p2[tid], bb = p2[256 + tid], cc = p2[512 + tid],
               d = p2[768 + tid];
        zi.x += a.x; zi.y += a.y; zf.x += bb.x; zf.y += bb.y;
        zg.x += cc.x; zg.y += cc.y; zo.x += d.x; zo.y += d.y;
      }
      const int j0 = tid * 2;
      float2 cold = *(float2*)&c[b * H_ + j0];
      float2 hn, cn;
      {
        const float ig = 1.f / (1.f + expf(-zi.x));
        const float fg = 1.f / (1.f + expf(-zf.x));
        const float gg = tanhf(zg.x);
        const float og = 1.f / (1.f + expf(-zo.x));
        cn.x = fg * cold.x + ig * gg;
        hn.x = og * tanhf(cn.x);
      }
      {
        const float ig = 1.f / (1.f + expf(-zi.y));
        const float fg = 1.f / (1.f + expf(-zf.y));
        const float gg = tanhf(zg.y);
        const float og = 1.f / (1.f + expf(-zo.y));
        cn.y = fg * cold.y + ig * gg;
        hn.y = og * tanhf(cn.y);
      }
      *(float2*)&c[b * H_ + j0] = cn;
      *(float2*)&h[b * H_ + j0] = hn;
      float2 outv = hn;
      if (apply_bn) {
        outv.x = (hn.x - bnm[j0]) * rsqrtf(bnv[j0] + EPS_) * bng[j0] + bnb[j0];
        outv.y = (hn.y - bnm[j0 + 1]) * rsqrtf(bnv[j0 + 1] + EPS_) *
                     bng[j0 + 1] + bnb[j0 + 1];
      }
      *(float2*)&seq[((size_t)b * T_ + t) * H_ + j0] = outv;
    }
    fast_bar(2 * t + 2);
  }
}

// ---------------- attention tail ------------------------------------------
__global__ __launch_bounds__(256) void rowsum_kernel(const float* __restrict__ e,
                                                     float* __restrict__ s) {
  const int row = blockIdx.x * 8 + (threadIdx.x >> 5);
  const int lane = threadIdx.x & 31;
  const float* p = e + (size_t)row * H_;
  float acc = 0.f;
  for (int j = lane; j < H_; j += 32) acc += p[j];
#pragma unroll
  for (int o = 16; o; o >>= 1) acc += __shfl_xor_sync(0xFFFFFFFFu, acc, o);
  if (lane == 0) s[row] = acc;
}

__global__ __launch_bounds__(512) void softmax_kernel(float* __restrict__ s) {
  __shared__ float red[T_];
  const int b = blockIdx.x, t = threadIdx.x;
  const float v = s[b * T_ + t];
  red[t] = v;
  __syncthreads();
  for (int o = 256; o; o >>= 1) {
    if (t < o) red[t] = fmaxf(red[t], red[t + o]);
    __syncthreads();
  }
  const float m = red[0];
  __syncthreads();
  const float ev = expf(v - m);
  red[t] = ev;
  __syncthreads();
  for (int o = 256; o; o >>= 1) {
    if (t < o) red[t] += red[t + o];
    __syncthreads();
  }
  s[b * T_ + t] = ev / red[0];
}

__global__ __launch_bounds__(512) void pool_kernel(const float* __restrict__ seq,
                                                   const float* __restrict__ a,
                                                   float* __restrict__ pool) {
  const int b = blockIdx.x, d = threadIdx.x;
  const float* p = seq + (size_t)b * T_ * H_ + d;
  const float* ap = a + b * T_;
  float acc = 0.f;
  for (int t = 0; t < T_; t++) acc += ap[t] * p[(size_t)t * H_];
  pool[b * H_ + d] = acc * (1.0f / T_);
}

// ---------------- dense head ----------------------------------------------
__global__ __launch_bounds__(128) void head_kernel(
    const float* __restrict__ pool,
    const float* __restrict__ Wd1, const float* __restrict__ bd1,
    const float* __restrict__ bng, const float* __restrict__ bnb,
    const float* __restrict__ bnm, const float* __restrict__ bnv,
    const float* __restrict__ Wd2, const float* __restrict__ bd2,
    const float* __restrict__ Wd3, const float* __restrict__ bd3,
    float* __restrict__ out) {
  __shared__ float sp[H_];
  __shared__ float d1[128];
  __shared__ float d2[64];
  const int b = blockIdx.x, t = threadIdx.x;
  for (int i = t; i < H_; i += 128) sp[i] = pool[b * H_ + i];
  __syncthreads();
  {
    float acc = bd1[t];
    for (int k = 0; k < H_; k++) acc += sp[k] * Wd1[k * 128 + t];
    acc = fmaxf(acc, 0.f);
    acc = (acc - bnm[t]) * rsqrtf(bnv[t] + EPS_) * bng[t] + bnb[t];
    d1[t] = acc;
  }
  __syncthreads();
  if (t < 64) {
    float acc = bd2[t];
    for (int k = 0; k < 128; k++) acc += d1[k] * Wd2[k * 64 + t];
    d2[t] = fmaxf(acc, 0.f);
  }
  __syncthreads();
  if (t < 5) {
    float acc = bd3[t];
    for (int k = 0; k < 64; k++) acc += d2[k] * Wd3[k * 5 + t];
    out[b * 5 + t] = acc;
  }
}

// ---------------- launch ----------------------------------------------------
extern "C" void kernel_launch(void* const* d_in, const int* in_sizes, int n_in,
                              void* d_out, int out_size) {
  (void)out_size;
  static const int sig_map[30] = {0, 1, 2, 3, 8, 9, 10, 15, 16, 17,
                                  4, 5, 6, 7, 11, 12, 13, 14, 22, 23,
                                  24, 25, 18, 19, 20, 21, 26, 27, 28, 29};
  const int setup_order = (n_in >= 5 && in_sizes[4] == 1048576) ? 1 : 0;
  const float* in[30];
  for (int i = 0; i < 30; i++)
    in[i] = (const float*)d_in[setup_order ? i : sig_map[i]];

  const float* x = in[0];
  const float* Wl[3] = {in[1], in[4], in[7]};
  const float* Ul[3] = {in[2], in[5], in[8]};
  const float* bl[3] = {in[3], in[6], in[9]};
  const float* bng[3] = {in[10], in[14], in[18]};
  const float* bnb[3] = {in[11], in[15], in[19]};
  const float* bnm[3] = {in[12], in[16], in[20]};
  const float* bnv[3] = {in[13], in[17], in[21]};
  const float* Wa = in[22];  const float* ba = in[23];
  const float* Wd1 = in[24]; const float* bd1 = in[25];
  const float* Wd2 = in[26]; const float* bd2 = in[27];
  const float* Wd3 = in[28]; const float* bd3 = in[29];

  float *xz, *seqA, *seqB, *h, *c, *part, *s, *pool;
  cudaGetSymbolAddress((void**)&xz, g_xz);
  cudaGetSymbolAddress((void**)&seqA, g_seqA);
  cudaGetSymbolAddress((void**)&seqB, g_seqB);
  cudaGetSymbolAddress((void**)&h, g_h);
  cudaGetSymbolAddress((void**)&c, g_c);
  cudaGetSymbolAddress((void**)&part, g_part);
  cudaGetSymbolAddress((void**)&s, g_s);
  cudaGetSymbolAddress((void**)&pool, g_pool);

  cudaFuncSetAttribute(lstm_layer_persist,
                       cudaFuncAttributeMaxDynamicSharedMemorySize, SMEM_SCAN);

  const int MROWS = B_ * T_;  // 65536
  float* seq_out[3] = {seqA, seqB, seqA};
  const float* seq_in[3] = {x, seqA, seqB};
  const int Kin[3] = {D_, H_, H_};

  for (int L = 0; L < 3; L++) {
    gemm_tf32<false><<<dim3(G_ / 128, MROWS / 128), 256>>>(
        seq_in[L], Wl[L], bl[L], xz, Kin[L], G_);
    const int apply_bn = (L < 2) ? 1 : 0;
    lstm_layer_persist<<<NBLK_, 256, SMEM_SCAN>>>(
        xz, Ul[L], seq_out[L], h, c, part,
        bng[L], bnb[L], bnm[L], bnv[L], apply_bn);
  }

  gemm_tf32<true><<<dim3(H_ / 128, MROWS / 128), 256>>>(seqA, Wa, ba, xz, H_,
                                                        H_);
  rowsum_kernel<<<MROWS / 8, 256>>>(xz, s);
  softmax_kernel<<<B_, T_>>>(s);
  pool_kernel<<<B_, H_>>>(seqA, s, pool);
  head_kernel<<<B_, 128>>>(pool, Wd1, bd1, bng[2], bnb[2], bnm[2], bnv[2],
                           Wd2, bd2, Wd3, bd3, (float*)d_out);
}